// round 5
// baseline (speedup 1.0000x reference)
#include <cuda_runtime.h>

#define N0 262144
#define N1 32768
#define N2 4096
#define BN_EPS 1e-5f

typedef unsigned long long u64;
typedef unsigned int u32;

__device__ __forceinline__ u64 pack2(float v) {
    u64 r; asm("mov.b64 %0, {%1, %1};" : "=l"(r) : "f"(v)); return r;
}
__device__ __forceinline__ void fma2(u64& d, u64 a, u64 b) {
    asm("fma.rn.f32x2 %0, %1, %2, %0;" : "+l"(d) : "l"(a), "l"(b));
}
__device__ __forceinline__ void unpack2(u64 v, float& lo, float& hi) {
    asm("mov.b64 {%0, %1}, %2;" : "=f"(lo), "=f"(hi) : "l"(v));
}
__device__ __forceinline__ void cp16(void* smem, const void* gmem) {
    u32 sa = (u32)__cvta_generic_to_shared(smem);
    asm volatile("cp.async.cg.shared.global [%0], [%1], 16;" :: "r"(sa), "l"(gmem));
}
__device__ __forceinline__ void cp_commit() { asm volatile("cp.async.commit_group;"); }
template <int W_> __device__ __forceinline__ void cp_wait() {
    asm volatile("cp.async.wait_group %0;" :: "n"(W_));
}

// ---------------- static scratch ----------------
__device__ float4 g_x4[N0];
__device__ float g_y0[N0 * 24];
__device__ float g_y1[N1 * 48];
__device__ float g_y2[N1 * 48];
__device__ float g_y3[N2 * 96];
__device__ float g_pC[3 * N1 * 48];
__device__ float g_pD[8 * N2 * 96];
__device__ float g_pE[9 * N2 * 96];
__device__ float g_stats[5 * 192];
__device__ float g_sb[5 * 192];
__device__ u32   g_ctr[8];

__global__ void init_kernel() {
    int t = threadIdx.x;
    for (int i = t; i < 5 * 192; i += 256) g_stats[i] = 0.f;
    if (t < 8) g_ctr[t] = 0u;
}

__global__ void pad_kernel(const float* __restrict__ d) {
    int i = blockIdx.x * 256 + threadIdx.x;
    if (i < N0) {
        float4 v;
        v.x = d[3 * i]; v.y = d[3 * i + 1]; v.z = d[3 * i + 2]; v.w = 0.f;
        g_x4[i] = v;
    }
}

// ---------------------------------------------------------------------------
// Fused gather + input-BN/ReLU + conv contraction.
//  - neighbor indices staged coalesced into smem (KT-sized k tiles)
//  - W slice in smem: full preload or cp.async double-buffered per k
//  - gathers software-pipelined one 8-channel chunk ahead
//  - FUSE: batch stats (sum/sumsq) reduced in epilogue, last block writes BN
//    scale/shift (requires no k/d split: KPB==K, DCHUNK==COUT).
// ---------------------------------------------------------------------------
template <int K, int KPB, int KT, int CIN, int XSTRIDE, int COUT, int DCHUNK,
          int R, int CH, bool NORM_IN, bool DBLBUF, bool FUSE>
__global__ void __launch_bounds__(256) conv_kernel(
    const float* __restrict__ x, const int* __restrict__ neigh,
    const float* __restrict__ W, const float* __restrict__ sb,
    float* __restrict__ y, int N,
    float* __restrict__ stats, const float* __restrict__ g,
    const float* __restrict__ b, float* __restrict__ sbout,
    u32* __restrict__ ctr, float invN)
{
    constexpr int WK = CIN * DCHUNK;
    constexpr int WSZ = DBLBUF ? 2 * WK : KPB * WK;
    constexpr int NH = CIN / CH;
    __shared__ __align__(16) float sh_w[WSZ];
    __shared__ int sh_idx[256 * R * KT];
    __shared__ float sh_s[NORM_IN ? 2 * CIN : 1];
    __shared__ float sh_stat[FUSE ? 16 * DCHUNK : 1];
    __shared__ bool s_last;

    const int tid = threadIdx.x;
    const int n0 = blockIdx.x * (256 * R);
    const int dbase = blockIdx.y * DCHUNK;
    const int k0 = blockIdx.z * KPB;
    const int n = n0 + tid * R;

    auto stageW = [&](int kk, int slot) {
        const float* src = W + (size_t)(k0 + kk) * CIN * COUT + dbase;
        float* dst = sh_w + slot * WK;
        #pragma unroll 1
        for (int i = tid; i < WK / 4; i += 256) {
            int c = i / (DCHUNK / 4), d4 = i % (DCHUNK / 4);
            cp16(dst + c * DCHUNK + d4 * 4, src + (size_t)c * COUT + d4 * 4);
        }
    };

    if (NORM_IN)
        for (int i = tid; i < 2 * CIN; i += 256) sh_s[i] = sb[i];

    if (DBLBUF) {
        stageW(0, 0); cp_commit();
    } else {
        #pragma unroll 1
        for (int kk = 0; kk < KPB; ++kk) stageW(kk, kk);
        cp_commit(); cp_wait<0>();
    }

    u64 acc[R][DCHUNK / 2] = {};

    #pragma unroll 1
    for (int kt = 0; kt < KPB; kt += KT) {
        __syncthreads();  // previous tile's sh_idx readers done
        #pragma unroll 1
        for (int i = tid; i < 256 * R * KT; i += 256) {
            int row = i / KT, kk = i % KT;
            sh_idx[i] = neigh[(size_t)(n0 + row) * K + k0 + kt + kk];
        }
        if (!DBLBUF) __syncthreads();

        #pragma unroll 1
        for (int k2 = 0; k2 < KT; ++k2) {
            const int kk = kt + k2;
            const float* wk;
            if (DBLBUF) {
                __syncthreads();  // prev slot consumers done (and idx staged)
                if (kk + 1 < KPB) { stageW(kk + 1, (kk + 1) & 1); cp_commit(); cp_wait<1>(); }
                else cp_wait<0>();
                __syncthreads();  // W(kk) + idx visible
                wk = sh_w + (kk & 1) * WK;
            } else {
                wk = sh_w + kk * WK;
            }

            int idxv[R];
            #pragma unroll
            for (int r = 0; r < R; ++r) idxv[r] = sh_idx[(tid * R + r) * KT + k2];

            if constexpr (CH == 3) {
                float4 v[R];
                #pragma unroll
                for (int r = 0; r < R; ++r)
                    v[r] = *(const float4*)(x + (size_t)idxv[r] * XSTRIDE);
                #pragma unroll
                for (int c = 0; c < 3; ++c) {
                    u64 xp[R];
                    #pragma unroll
                    for (int r = 0; r < R; ++r)
                        xp[r] = pack2(c == 0 ? v[r].x : (c == 1 ? v[r].y : v[r].z));
                    const ulonglong2* wr = (const ulonglong2*)(wk + c * DCHUNK);
                    #pragma unroll
                    for (int j = 0; j < DCHUNK / 4; ++j) {
                        ulonglong2 wv = wr[j];
                        #pragma unroll
                        for (int r = 0; r < R; ++r) {
                            fma2(acc[r][2 * j],     xp[r], wv.x);
                            fma2(acc[r][2 * j + 1], xp[r], wv.y);
                        }
                    }
                }
            } else {
                // CH == 8, R == 1, pipelined 8-channel chunks
                const float4* xr = (const float4*)(x + (size_t)idxv[0] * XSTRIDE);
                float4 a0 = xr[0], a1 = xr[1];
                #pragma unroll 1
                for (int h = 0; h < NH; ++h) {
                    float4 b0 = a0, b1 = a1;
                    if (h + 1 < NH) { b0 = xr[2 * h + 2]; b1 = xr[2 * h + 3]; }
                    float xv[8] = {a0.x, a0.y, a0.z, a0.w, a1.x, a1.y, a1.z, a1.w};
                    if (NORM_IN) {
                        #pragma unroll
                        for (int j = 0; j < 8; ++j)
                            xv[j] = fmaxf(xv[j] * sh_s[h * 8 + j] + sh_s[CIN + h * 8 + j], 0.f);
                    }
                    #pragma unroll
                    for (int c = 0; c < 8; ++c) {
                        u64 xp = pack2(xv[c]);
                        const ulonglong2* wr = (const ulonglong2*)(wk + (h * 8 + c) * DCHUNK);
                        #pragma unroll
                        for (int j = 0; j < DCHUNK / 4; ++j) {
                            ulonglong2 wv = wr[j];
                            fma2(acc[0][2 * j],     xp, wv.x);
                            fma2(acc[0][2 * j + 1], xp, wv.y);
                        }
                    }
                    a0 = b0; a1 = b1;
                }
            }
        }
    }

    // store
    #pragma unroll
    for (int r = 0; r < R; ++r) {
        float* yr = y + ((size_t)blockIdx.z * N + (n + r)) * COUT + dbase;
        #pragma unroll
        for (int j = 0; j < DCHUNK / 4; ++j) {
            float4 v;
            unpack2(acc[r][2 * j],     v.x, v.y);
            unpack2(acc[r][2 * j + 1], v.z, v.w);
            *(float4*)(yr + 4 * j) = v;
        }
    }

    if (FUSE) {
        const int wid = tid >> 5;
        #pragma unroll 1
        for (int j = 0; j < DCHUNK / 2; ++j) {
            float lo = 0.f, hi = 0.f, qlo = 0.f, qhi = 0.f;
            #pragma unroll
            for (int r = 0; r < R; ++r) {
                float l, h2; unpack2(acc[r][j], l, h2);
                lo += l; hi += h2; qlo += l * l; qhi += h2 * h2;
            }
            #pragma unroll
            for (int o = 16; o; o >>= 1) {
                lo  += __shfl_xor_sync(~0u, lo,  o);
                hi  += __shfl_xor_sync(~0u, hi,  o);
                qlo += __shfl_xor_sync(~0u, qlo, o);
                qhi += __shfl_xor_sync(~0u, qhi, o);
            }
            if ((tid & 31) == 0) {
                float* row = sh_stat + wid * 2 * DCHUNK;
                row[2 * j] = lo;  row[2 * j + 1] = hi;
                row[DCHUNK + 2 * j] = qlo;  row[DCHUNK + 2 * j + 1] = qhi;
            }
        }
        __syncthreads();
        if (tid < 2 * DCHUNK) {
            float t = 0.f;
            #pragma unroll
            for (int w = 0; w < 8; ++w) t += sh_stat[w * 2 * DCHUNK + tid];
            atomicAdd(&stats[tid], t);
        }
        __syncthreads();
        if (tid == 0) {
            __threadfence();
            s_last = (atomicAdd(ctr, 1u) == gridDim.x - 1);
        }
        __syncthreads();
        if (s_last && tid < COUT) {
            float su = __ldcg(&stats[tid]);
            float qq = __ldcg(&stats[COUT + tid]);
            float mu = su * invN;
            float var = fmaxf(qq * invN - mu * mu, 0.f);
            float sc = g[tid] * rsqrtf(var + BN_EPS);
            sbout[tid] = sc;
            sbout[COUT + tid] = b[tid] - mu * sc;
        }
    }
}

// ---------------------------------------------------------------------------
// Combine KZ partials -> y (float4 lanes), stats, last-block BN finalize.
// blockDim = (C/4, TB).
// ---------------------------------------------------------------------------
template <int C, int KZ, int TB, bool WRITE_Y>
__global__ void __launch_bounds__(256) combine_kernel(
    const float* __restrict__ p, float* __restrict__ y, int N,
    float* __restrict__ stats, const float* __restrict__ g,
    const float* __restrict__ b, float* __restrict__ sbout,
    u32* __restrict__ ctr, float invN)
{
    constexpr int V4 = C / 4;
    const int c4 = threadIdx.x;
    const int ty = threadIdx.y;

    float4 s = make_float4(0.f, 0.f, 0.f, 0.f);
    float4 q = make_float4(0.f, 0.f, 0.f, 0.f);

    #pragma unroll 2
    for (int r = blockIdx.x * TB + ty; r < N; r += gridDim.x * TB) {
        float4 v = *(const float4*)(p + (size_t)r * C + 4 * c4);
        #pragma unroll
        for (int z = 1; z < KZ; ++z) {
            float4 t = *(const float4*)(p + ((size_t)z * N + r) * C + 4 * c4);
            v.x += t.x; v.y += t.y; v.z += t.z; v.w += t.w;
        }
        if (WRITE_Y) *(float4*)(y + (size_t)r * C + 4 * c4) = v;
        s.x += v.x; s.y += v.y; s.z += v.z; s.w += v.w;
        q.x += v.x * v.x; q.y += v.y * v.y; q.z += v.z * v.z; q.w += v.w * v.w;
    }

    __shared__ float4 shs[TB][V4];
    __shared__ float4 shq[TB][V4];
    __shared__ bool last;
    shs[ty][c4] = s; shq[ty][c4] = q;
    __syncthreads();

    if (ty == 0) {
        #pragma unroll 4
        for (int j = 1; j < TB; ++j) {
            float4 a = shs[j][c4], d = shq[j][c4];
            s.x += a.x; s.y += a.y; s.z += a.z; s.w += a.w;
            q.x += d.x; q.y += d.y; q.z += d.z; q.w += d.w;
        }
        atomicAdd(&stats[4 * c4 + 0], s.x);
        atomicAdd(&stats[4 * c4 + 1], s.y);
        atomicAdd(&stats[4 * c4 + 2], s.z);
        atomicAdd(&stats[4 * c4 + 3], s.w);
        atomicAdd(&stats[C + 4 * c4 + 0], q.x);
        atomicAdd(&stats[C + 4 * c4 + 1], q.y);
        atomicAdd(&stats[C + 4 * c4 + 2], q.z);
        atomicAdd(&stats[C + 4 * c4 + 3], q.w);
        __threadfence();
    }
    __syncthreads();
    if (ty == 0 && c4 == 0)
        last = (atomicAdd(ctr, 1u) == gridDim.x - 1);
    __syncthreads();
    if (last && ty == 0) {
        #pragma unroll
        for (int j = 0; j < 4; ++j) {
            int c = 4 * c4 + j;
            float su = __ldcg(&stats[c]);
            float qq = __ldcg(&stats[C + c]);
            float mu = su * invN;
            float var = fmaxf(qq * invN - mu * mu, 0.f);
            float sc = g[c] * rsqrtf(var + BN_EPS);
            sbout[c] = sc;
            sbout[C + c] = b[c] - mu * sc;
        }
    }
}

__global__ void norm_out_kernel(float* __restrict__ out, const float* __restrict__ sb) {
    int i = blockIdx.x * 256 + threadIdx.x;
    if (i < N2 * 96) {
        int c = i % 96;
        out[i] = fmaxf(out[i] * sb[c] + sb[96 + c], 0.f);
    }
}

// ---------------------------------------------------------------------------
extern "C" void kernel_launch(void* const* d_in, const int* in_sizes, int n_in,
                              void* d_out, int out_size)
{
    const float* data   = (const float*)d_in[0];
    const int* neigh0 = (const int*)d_in[1];
    const int* child0 = (const int*)d_in[2];
    const int* neigh1 = (const int*)d_in[3];
    const int* child1 = (const int*)d_in[4];
    const int* neigh2 = (const int*)d_in[5];
    const float* w0 = (const float*)d_in[6];
    const float* g0 = (const float*)d_in[7];
    const float* b0 = (const float*)d_in[8];
    const float* wd0 = (const float*)d_in[9];
    const float* gd0 = (const float*)d_in[10];
    const float* bd0 = (const float*)d_in[11];
    const float* w1 = (const float*)d_in[12];
    const float* g1 = (const float*)d_in[13];
    const float* b1 = (const float*)d_in[14];
    const float* wd1 = (const float*)d_in[15];
    const float* gd1 = (const float*)d_in[16];
    const float* bd1 = (const float*)d_in[17];
    const float* wp = (const float*)d_in[18];
    const float* gp = (const float*)d_in[19];
    const float* bp = (const float*)d_in[20];
    float* out = (float*)d_out;

    float *x4p, *y0p, *y1p, *y2p, *y3p, *pCp, *pDp, *pEp, *stp, *sbp;
    u32* ctrp;
    cudaGetSymbolAddress((void**)&x4p, g_x4);
    cudaGetSymbolAddress((void**)&y0p, g_y0);
    cudaGetSymbolAddress((void**)&y1p, g_y1);
    cudaGetSymbolAddress((void**)&y2p, g_y2);
    cudaGetSymbolAddress((void**)&y3p, g_y3);
    cudaGetSymbolAddress((void**)&pCp, g_pC);
    cudaGetSymbolAddress((void**)&pDp, g_pD);
    cudaGetSymbolAddress((void**)&pEp, g_pE);
    cudaGetSymbolAddress((void**)&stp, g_stats);
    cudaGetSymbolAddress((void**)&sbp, g_sb);
    cudaGetSymbolAddress((void**)&ctrp, g_ctr);

    init_kernel<<<1, 256>>>();
    pad_kernel<<<N0 / 256, 256>>>(data);

    // A: x4 -> y0[N0,24]; K=27 preload, R=2, fused stats+finalize
    conv_kernel<27, 27, 9, 3, 4, 24, 24, 2, 3, false, false, true>
        <<<dim3(512, 1, 1), 256>>>(x4p, neigh0, w0, nullptr, y0p, N0,
                                   stp + 0, g0, b0, sbp + 0, ctrp + 0, 1.f / N0);

    // B: y0 -> y1[N1,48]; K=8 dbl-buffered, fused stats+finalize
    conv_kernel<8, 8, 8, 24, 24, 48, 48, 1, 8, true, true, true>
        <<<dim3(128, 1, 1), 256>>>(y0p, child0, wd0, sbp + 0, y1p, N1,
                                   stp + 192, gd0, bd0, sbp + 192, ctrp + 1, 1.f / N1);

    // C: y1 -> pC (kz=3, KPB=9 dbl-buffered, full 48 out per thread) -> y2
    conv_kernel<27, 9, 9, 48, 48, 48, 48, 1, 8, true, true, false>
        <<<dim3(128, 1, 3), 256>>>(y1p, neigh1, w1, sbp + 192, pCp, N1,
                                   nullptr, nullptr, nullptr, nullptr, nullptr, 0.f);
    combine_kernel<48, 3, 21, true><<<512, dim3(12, 21)>>>(
        pCp, y2p, N1, stp + 384, g1, b1, sbp + 384, ctrp + 2, 1.f / N1);

    // D: y2 -> pD (kz=8, d-split 2) -> y3[N2,96]
    conv_kernel<8, 1, 1, 48, 48, 96, 48, 1, 8, true, false, false>
        <<<dim3(16, 2, 8), 256>>>(y2p, child1, wd1, sbp + 384, pDp, N2,
                                  nullptr, nullptr, nullptr, nullptr, nullptr, 0.f);
    combine_kernel<96, 8, 10, true><<<256, dim3(24, 10)>>>(
        pDp, y3p, N2, stp + 576, gd1, bd1, sbp + 576, ctrp + 3, 1.f / N2);

    // E: y3 -> pE (kz=9, KPB=3 dbl-buffered, d-split 2) -> out raw
    conv_kernel<27, 3, 3, 96, 96, 96, 48, 1, 8, true, true, false>
        <<<dim3(16, 2, 9), 256>>>(y3p, neigh2, wp, sbp + 576, pEp, N2,
                                  nullptr, nullptr, nullptr, nullptr, nullptr, 0.f);
    combine_kernel<96, 9, 10, true><<<256, dim3(24, 10)>>>(
        pEp, out, N2, stp + 768, gp, bp, sbp + 768, ctrp + 4, 1.f / N2);

    norm_out_kernel<<<(N2 * 96 + 255) / 256, 256>>>(out, sbp + 768);
}